// round 2
// baseline (speedup 1.0000x reference)
#include <cuda_runtime.h>
#include <stdint.h>

// ============================================================================
// SpecAugment, bit-exact vs JAX threefry2x32 (partitionable mode).
// R2: mask math hoisted out of the streaming kernel.
//   setup_kernel: 64 blocks (one per batch). 7 lanes compute the RNG draws
//     (identical math to the verified R1 kernel), then the block materializes
//     - g_rz[row]   : 1 byte per (b,m) row  -> freq-masked row
//     - g_tm4[b][i] : 1 nibble per float4 group (bit k = t=4i+k time-masked)
//   apply_kernel: per float4: nibble LDG.U8 + smem float4 LUT multiply.
// ============================================================================

#define BATCH 64
#define NMELS 80
#define TLEN 4000
#define NQ (TLEN / 4)          // 1000 float4 groups per row

__device__ uint8_t g_rz[BATCH * NMELS];   // 5120 B
__device__ uint8_t g_tm4[BATCH * NQ];     // 64000 B

__device__ __forceinline__ uint32_t rotl32(uint32_t x, int d) {
    return (x << d) | (x >> (32 - d));
}

__device__ __forceinline__ void tf2x32(uint32_t k0, uint32_t k1,
                                       uint32_t c0, uint32_t c1,
                                       uint32_t& o0, uint32_t& o1) {
    const uint32_t ks0 = k0, ks1 = k1, ks2 = 0x1BD11BDAu ^ k0 ^ k1;
    uint32_t x0 = c0 + ks0, x1 = c1 + ks1;
#define TF_RND(r) { x0 += x1; x1 = rotl32(x1, r); x1 ^= x0; }
    TF_RND(13) TF_RND(15) TF_RND(26) TF_RND(6)
    x0 += ks1; x1 += ks2 + 1u;
    TF_RND(17) TF_RND(29) TF_RND(16) TF_RND(24)
    x0 += ks2; x1 += ks0 + 2u;
    TF_RND(13) TF_RND(15) TF_RND(26) TF_RND(6)
    x0 += ks0; x1 += ks1 + 3u;
    TF_RND(17) TF_RND(29) TF_RND(16) TF_RND(24)
    x0 += ks1; x1 += ks2 + 4u;
    TF_RND(13) TF_RND(15) TF_RND(26) TF_RND(6)
    x0 += ks2; x1 += ks0 + 5u;
#undef TF_RND
    o0 = x0; o1 = x1;
}

__device__ __forceinline__ uint32_t randbits32(uint32_t k0, uint32_t k1, uint32_t idx) {
    uint32_t a, b;
    tf2x32(k0, k1, 0u, idx, a, b);
    return a ^ b;
}

__device__ __forceinline__ float u32_to_unif(uint32_t bits) {
    return __uint_as_float((bits >> 9) | 0x3f800000u) - 1.0f;
}

// One block per batch. Lanes 0..4: time masks; lanes 5..6: freq masks.
__global__ void __launch_bounds__(256) setup_kernel(const int* __restrict__ lengths) {
    __shared__ int s_t0[5], s_tl[5], s_f0[2], s_fl[2];
    const int b = blockIdx.x;
    const int tid = threadIdx.x;

    if (tid < 5) {
        // time mask j = tid. keys: kt_w = fold(base, 2), kt_s = fold(base, 3)
        int j = tid;
        uint32_t ktw0, ktw1, kts0, kts1;
        tf2x32(0u, 42u, 0u, 2u, ktw0, ktw1);
        tf2x32(0u, 42u, 0u, 3u, kts0, kts1);
        int valid = lengths[b];
        int mt = (int)((float)valid * 0.05f);
        int max_t = min(25, mt);
        max_t = min(max_t, valid - 1);
        max_t = max(0, max_t);
        uint32_t i = (uint32_t)(b * 5 + j);
        float ut = u32_to_unif(randbits32(ktw0, ktw1, i));
        int t = (int)floorf(ut * (float)(max_t + 1));
        if (valid <= 1) t = 0;
        float ut0 = u32_to_unif(randbits32(kts0, kts1, i));
        int t0 = (int)floorf(ut0 * (float)(valid - t + 1));
        s_t0[j] = t0;
        s_tl[j] = t;
    } else if (tid < 7) {
        // freq mask j = tid-5. keys: kf_w = fold(base,0) -> klo = fold(kf_w,1);
        // kf_s = fold(base, 1)
        int j = tid - 5;
        uint32_t kfw0, kfw1, kfs0, kfs1, klo0, klo1;
        tf2x32(0u, 42u, 0u, 0u, kfw0, kfw1);
        tf2x32(0u, 42u, 0u, 1u, kfs0, kfs1);
        tf2x32(kfw0, kfw1, 0u, 1u, klo0, klo1);
        uint32_t i = (uint32_t)(b * 2 + j);
        int f = (int)(randbits32(klo0, klo1, i) & 15u);
        float uf = u32_to_unif(randbits32(kfs0, kfs1, i));
        int f0 = (int)floorf(uf * (float)(NMELS - f + 1));
        s_f0[j] = f0;
        s_fl[j] = f;
    }
    __syncthreads();

    // per-row freq-zero byte
    if (tid < NMELS) {
        int m = tid;
        bool z = ((unsigned)(m - s_f0[0]) < (unsigned)s_fl[0]) |
                 ((unsigned)(m - s_f0[1]) < (unsigned)s_fl[1]);
        g_rz[b * NMELS + m] = z ? 1 : 0;
    }

    // per-float4-group time nibble
    for (int i = tid; i < NQ; i += 256) {
        int t = i * 4;
        unsigned nib = 0;
#pragma unroll
        for (int j = 0; j < 5; j++) {
            int t0 = s_t0[j];
            unsigned len = (unsigned)s_tl[j];
            nib |= ((unsigned)(t     - t0) < len) ? 1u : 0u;
            nib |= ((unsigned)(t + 1 - t0) < len) ? 2u : 0u;
            nib |= ((unsigned)(t + 2 - t0) < len) ? 4u : 0u;
            nib |= ((unsigned)(t + 3 - t0) < len) ? 8u : 0u;
        }
        g_tm4[b * NQ + i] = (uint8_t)nib;
    }
}

// grid = (4, BATCH*NMELS); one float4 per thread.
__global__ void __launch_bounds__(256) apply_kernel(const float* __restrict__ mel,
                                                    float* __restrict__ out) {
    __shared__ float4 s_lut[16];
    if (threadIdx.x < 16) {
        unsigned n = threadIdx.x;
        s_lut[n] = make_float4((n & 1u) ? 0.f : 1.f,
                               (n & 2u) ? 0.f : 1.f,
                               (n & 4u) ? 0.f : 1.f,
                               (n & 8u) ? 0.f : 1.f);
    }
    __syncthreads();

    const int row = blockIdx.y;                 // b*NMELS + m
    const int i = blockIdx.x * 256 + threadIdx.x;
    if (i >= NQ) return;

    const int b = row / NMELS;                  // const-div -> mul/shift
    unsigned nib = g_tm4[b * NQ + i];
    if (g_rz[row]) nib = 15u;                   // whole row zeroed

    const size_t off = (size_t)row * TLEN + (size_t)(i * 4);
    float4 v = *reinterpret_cast<const float4*>(mel + off);
    const float4 msk = s_lut[nib];
    v.x *= msk.x;
    v.y *= msk.y;
    v.z *= msk.z;
    v.w *= msk.w;
    *reinterpret_cast<float4*>(out + off) = v;
}

extern "C" void kernel_launch(void* const* d_in, const int* in_sizes, int n_in,
                              void* d_out, int out_size) {
    const float* mel = (const float*)d_in[0];
    const int* lengths = (const int*)d_in[1];
    float* out = (float*)d_out;

    setup_kernel<<<BATCH, 256>>>(lengths);
    dim3 grid((NQ + 255) / 256, BATCH * NMELS);
    apply_kernel<<<grid, 256>>>(mel, out);
}

// round 3
// speedup vs baseline: 1.0615x; 1.0615x over previous
#include <cuda_runtime.h>
#include <stdint.h>

// ============================================================================
// SpecAugment, bit-exact vs JAX threefry2x32 (partitionable mode).
// R3: (1) constexpr threefry key folds (SEED-only dependent) -> setup lanes do
//     2 chains instead of 6-7; (2) apply processes 4 float4/thread (stride-256,
//     fully coalesced) for 4x memory-level parallelism; streaming ld/st hints.
// ============================================================================

#define BATCH 64
#define NMELS 80
#define TLEN 4000
#define NQ (TLEN / 4)          // 1000 float4 groups per row

__device__ uint8_t g_rz[BATCH * NMELS];   // per-row freq-zero byte
__device__ uint8_t g_tm4[BATCH * NQ];     // per-float4-group time nibble

// ---------------- threefry2x32, constexpr-capable ----------------
struct U2 { uint32_t a, b; };

__host__ __device__ constexpr uint32_t rotl32c(uint32_t x, int d) {
    return (x << d) | (x >> (32 - d));
}

__host__ __device__ constexpr U2 tf2x32(uint32_t k0, uint32_t k1,
                                        uint32_t c0, uint32_t c1) {
    const uint32_t ks0 = k0, ks1 = k1, ks2 = 0x1BD11BDAu ^ k0 ^ k1;
    uint32_t x0 = c0 + ks0, x1 = c1 + ks1;
#define TF_RND(r) { x0 += x1; x1 = rotl32c(x1, r); x1 ^= x0; }
    TF_RND(13) TF_RND(15) TF_RND(26) TF_RND(6)
    x0 += ks1; x1 += ks2 + 1u;
    TF_RND(17) TF_RND(29) TF_RND(16) TF_RND(24)
    x0 += ks2; x1 += ks0 + 2u;
    TF_RND(13) TF_RND(15) TF_RND(26) TF_RND(6)
    x0 += ks0; x1 += ks1 + 3u;
    TF_RND(17) TF_RND(29) TF_RND(16) TF_RND(24)
    x0 += ks1; x1 += ks2 + 4u;
    TF_RND(13) TF_RND(15) TF_RND(26) TF_RND(6)
    x0 += ks2; x1 += ks0 + 5u;
#undef TF_RND
    return U2{x0, x1};
}

// Compile-time key folds: split(key(42), 4) and randint's internal split.
constexpr U2 KFW = tf2x32(0u, 42u, 0u, 0u);            // kf_w
constexpr U2 KFS = tf2x32(0u, 42u, 0u, 1u);            // kf_s
constexpr U2 KTW = tf2x32(0u, 42u, 0u, 2u);            // kt_w
constexpr U2 KTS = tf2x32(0u, 42u, 0u, 3u);            // kt_s
constexpr U2 KLO = tf2x32(KFW.a, KFW.b, 0u, 1u);       // randint lower-bits key

__device__ __forceinline__ uint32_t randbits32(uint32_t k0, uint32_t k1, uint32_t idx) {
    U2 r = tf2x32(k0, k1, 0u, idx);
    return r.a ^ r.b;
}

__device__ __forceinline__ float u32_to_unif(uint32_t bits) {
    return __uint_as_float((bits >> 9) | 0x3f800000u) - 1.0f;
}

// ---------------- setup: one block per batch ----------------
__global__ void __launch_bounds__(256) setup_kernel(const int* __restrict__ lengths) {
    __shared__ int s_t0[5], s_tl[5], s_f0[2], s_fl[2];
    const int b = blockIdx.x;
    const int tid = threadIdx.x;

    if (tid < 5) {
        // time mask j = tid: 2 threefry chains (keys are immediates)
        int j = tid;
        int valid = lengths[b];
        int mt = (int)((float)valid * 0.05f);
        int max_t = min(25, mt);
        max_t = min(max_t, valid - 1);
        max_t = max(0, max_t);
        uint32_t i = (uint32_t)(b * 5 + j);
        float ut = u32_to_unif(randbits32(KTW.a, KTW.b, i));
        int t = (int)floorf(ut * (float)(max_t + 1));
        if (valid <= 1) t = 0;
        float ut0 = u32_to_unif(randbits32(KTS.a, KTS.b, i));
        int t0 = (int)floorf(ut0 * (float)(valid - t + 1));
        s_t0[j] = t0;
        s_tl[j] = t;
    } else if (tid < 7) {
        // freq mask j = tid-5: 2 threefry chains
        int j = tid - 5;
        uint32_t i = (uint32_t)(b * 2 + j);
        int f = (int)(randbits32(KLO.a, KLO.b, i) & 15u);
        float uf = u32_to_unif(randbits32(KFS.a, KFS.b, i));
        int f0 = (int)floorf(uf * (float)(NMELS - f + 1));
        s_f0[j] = f0;
        s_fl[j] = f;
    }
    __syncthreads();

    if (tid < NMELS) {
        int m = tid;
        bool z = ((unsigned)(m - s_f0[0]) < (unsigned)s_fl[0]) |
                 ((unsigned)(m - s_f0[1]) < (unsigned)s_fl[1]);
        g_rz[b * NMELS + m] = z ? 1 : 0;
    }

#pragma unroll
    for (int k = 0; k < 4; k++) {
        int i = tid + k * 256;
        if (i >= NQ) break;
        int t = i * 4;
        unsigned nib = 0;
#pragma unroll
        for (int j = 0; j < 5; j++) {
            int t0 = s_t0[j];
            unsigned len = (unsigned)s_tl[j];
            nib |= ((unsigned)(t     - t0) < len) ? 1u : 0u;
            nib |= ((unsigned)(t + 1 - t0) < len) ? 2u : 0u;
            nib |= ((unsigned)(t + 2 - t0) < len) ? 4u : 0u;
            nib |= ((unsigned)(t + 3 - t0) < len) ? 8u : 0u;
        }
        g_tm4[b * NQ + i] = (uint8_t)nib;
    }
}

// ---------------- apply: 1 block per row, 4 float4 per thread ----------------
__global__ void __launch_bounds__(256) apply_kernel(const float* __restrict__ mel,
                                                    float* __restrict__ out) {
    __shared__ float4 s_lut[16];
    if (threadIdx.x < 16) {
        unsigned n = threadIdx.x;
        s_lut[n] = make_float4((n & 1u) ? 0.f : 1.f,
                               (n & 2u) ? 0.f : 1.f,
                               (n & 4u) ? 0.f : 1.f,
                               (n & 8u) ? 0.f : 1.f);
    }
    __syncthreads();

    const int row = blockIdx.x;                 // b*NMELS + m
    const int b = row / NMELS;
    const int tid = threadIdx.x;
    const unsigned rz = g_rz[row];              // uniform per block
    const float* mrow = mel + (size_t)row * TLEN;
    float* orow = out + (size_t)row * TLEN;
    const uint8_t* nrow = g_tm4 + b * NQ;

    int idx[4];
    bool act[4];
    unsigned nib[4];
    float4 v[4];
#pragma unroll
    for (int k = 0; k < 4; k++) {
        idx[k] = tid + k * 256;
        act[k] = idx[k] < NQ;
    }
    // issue all mask + data loads up front (4x MLP)
#pragma unroll
    for (int k = 0; k < 4; k++)
        nib[k] = act[k] ? nrow[idx[k]] : 0u;
#pragma unroll
    for (int k = 0; k < 4; k++)
        if (act[k]) v[k] = __ldcs(reinterpret_cast<const float4*>(mrow + idx[k] * 4));
#pragma unroll
    for (int k = 0; k < 4; k++) {
        if (!act[k]) continue;
        unsigned n = rz ? 15u : nib[k];
        const float4 msk = s_lut[n];
        v[k].x *= msk.x;
        v[k].y *= msk.y;
        v[k].z *= msk.z;
        v[k].w *= msk.w;
        __stcs(reinterpret_cast<float4*>(orow + idx[k] * 4), v[k]);
    }
}

extern "C" void kernel_launch(void* const* d_in, const int* in_sizes, int n_in,
                              void* d_out, int out_size) {
    const float* mel = (const float*)d_in[0];
    const int* lengths = (const int*)d_in[1];
    float* out = (float*)d_out;

    setup_kernel<<<BATCH, 256>>>(lengths);
    apply_kernel<<<BATCH * NMELS, 256>>>(mel, out);
}

// round 4
// speedup vs baseline: 1.1333x; 1.0677x over previous
#include <cuda_runtime.h>
#include <stdint.h>

// ============================================================================
// SpecAugment, bit-exact vs JAX threefry2x32 (partitionable mode).
// R4: single fused kernel. Grid = 64 batches x 16 chunks; each block handles
// 5 rows of one batch. Prologue: 7 lanes do the threefry draws (constexpr
// keys), 125 lanes build a 4000-bit time mask in smem via interval spans.
// Hot loop: 4 float4/thread per row, LUT multiply; freq-masked rows skip the
// load and store zeros directly.
// ============================================================================

#define BATCH 64
#define NMELS 80
#define TLEN 4000
#define NQ (TLEN / 4)          // 1000 float4 groups per row
#define CHUNKS 16
#define ROWS_PER_BLK (NMELS / CHUNKS)   // 5

// ---------------- threefry2x32, constexpr-capable ----------------
struct U2 { uint32_t a, b; };

__host__ __device__ constexpr uint32_t rotl32c(uint32_t x, int d) {
    return (x << d) | (x >> (32 - d));
}

__host__ __device__ constexpr U2 tf2x32(uint32_t k0, uint32_t k1,
                                        uint32_t c0, uint32_t c1) {
    const uint32_t ks0 = k0, ks1 = k1, ks2 = 0x1BD11BDAu ^ k0 ^ k1;
    uint32_t x0 = c0 + ks0, x1 = c1 + ks1;
#define TF_RND(r) { x0 += x1; x1 = rotl32c(x1, r); x1 ^= x0; }
    TF_RND(13) TF_RND(15) TF_RND(26) TF_RND(6)
    x0 += ks1; x1 += ks2 + 1u;
    TF_RND(17) TF_RND(29) TF_RND(16) TF_RND(24)
    x0 += ks2; x1 += ks0 + 2u;
    TF_RND(13) TF_RND(15) TF_RND(26) TF_RND(6)
    x0 += ks0; x1 += ks1 + 3u;
    TF_RND(17) TF_RND(29) TF_RND(16) TF_RND(24)
    x0 += ks1; x1 += ks2 + 4u;
    TF_RND(13) TF_RND(15) TF_RND(26) TF_RND(6)
    x0 += ks2; x1 += ks0 + 5u;
#undef TF_RND
    return U2{x0, x1};
}

// Compile-time key folds: split(key(42), 4) and randint's internal split.
constexpr U2 KFW = tf2x32(0u, 42u, 0u, 0u);            // kf_w
constexpr U2 KFS = tf2x32(0u, 42u, 0u, 1u);            // kf_s
constexpr U2 KTW = tf2x32(0u, 42u, 0u, 2u);            // kt_w
constexpr U2 KTS = tf2x32(0u, 42u, 0u, 3u);            // kt_s
constexpr U2 KLO = tf2x32(KFW.a, KFW.b, 0u, 1u);       // randint lower-bits key

__device__ __forceinline__ uint32_t randbits32(uint32_t k0, uint32_t k1, uint32_t idx) {
    U2 r = tf2x32(k0, k1, 0u, idx);
    return r.a ^ r.b;
}

__device__ __forceinline__ float u32_to_unif(uint32_t bits) {
    return __uint_as_float((bits >> 9) | 0x3f800000u) - 1.0f;
}

// ---------------- fused kernel ----------------
__global__ void __launch_bounds__(256) fused_kernel(const float* __restrict__ mel,
                                                    const int* __restrict__ lengths,
                                                    float* __restrict__ out) {
    __shared__ int s_t0[5], s_tl[5], s_f0[2], s_fl[2];
    __shared__ uint32_t s_bits[NQ / 8];   // 4000 bits = 125 words
    __shared__ float4 s_lut[16];

    const int b = blockIdx.x >> 4;        // batch
    const int chunk = blockIdx.x & 15;    // 5-row chunk within batch
    const int tid = threadIdx.x;

    // -- RNG draws (identical math to verified R1-R3) --
    if (tid < 5) {
        int j = tid;
        int valid = lengths[b];
        int mt = (int)((float)valid * 0.05f);
        int max_t = min(25, mt);
        max_t = min(max_t, valid - 1);
        max_t = max(0, max_t);
        uint32_t i = (uint32_t)(b * 5 + j);
        float ut = u32_to_unif(randbits32(KTW.a, KTW.b, i));
        int t = (int)floorf(ut * (float)(max_t + 1));
        if (valid <= 1) t = 0;
        float ut0 = u32_to_unif(randbits32(KTS.a, KTS.b, i));
        int t0 = (int)floorf(ut0 * (float)(valid - t + 1));
        s_t0[j] = t0;
        s_tl[j] = t;
    } else if (tid < 7) {
        int j = tid - 5;
        uint32_t i = (uint32_t)(b * 2 + j);
        int f = (int)(randbits32(KLO.a, KLO.b, i) & 15u);
        float uf = u32_to_unif(randbits32(KFS.a, KFS.b, i));
        int f0 = (int)floorf(uf * (float)(NMELS - f + 1));
        s_f0[j] = f0;
        s_fl[j] = f;
    }
    if (tid < 16) {
        unsigned n = tid;
        s_lut[n] = make_float4((n & 1u) ? 0.f : 1.f,
                               (n & 2u) ? 0.f : 1.f,
                               (n & 4u) ? 0.f : 1.f,
                               (n & 8u) ? 0.f : 1.f);
    }
    __syncthreads();

    // -- build 4000-bit time mask via interval spans (element e -> word e/32) --
    if (tid < NQ / 8) {
        const int base = tid * 32;
        uint32_t w = 0;
#pragma unroll
        for (int j = 0; j < 5; j++) {
            int lo = max(s_t0[j], base);
            int hi = min(s_t0[j] + s_tl[j], base + 32);
            if (hi > lo)
                w |= (uint32_t)(((1ull << (hi - lo)) - 1ull) << (lo - base));
        }
        s_bits[tid] = w;
    }
    __syncthreads();

    const int f00 = s_f0[0], fl0 = s_fl[0], f01 = s_f0[1], fl1 = s_fl[1];

    // -- stream 5 rows --
#pragma unroll
    for (int r = 0; r < ROWS_PER_BLK; r++) {
        const int m = chunk * ROWS_PER_BLK + r;
        const int row = b * NMELS + m;
        const float* mrow = mel + (size_t)row * TLEN;
        float* orow = out + (size_t)row * TLEN;
        const bool rz = ((unsigned)(m - f00) < (unsigned)fl0) |
                        ((unsigned)(m - f01) < (unsigned)fl1);

        if (rz) {
            const float4 z = make_float4(0.f, 0.f, 0.f, 0.f);
#pragma unroll
            for (int k = 0; k < 4; k++) {
                int idx = tid + k * 256;
                if (idx < NQ)
                    __stcs(reinterpret_cast<float4*>(orow + idx * 4), z);
            }
        } else {
            int idx[4];
            bool act[4];
            unsigned nib[4];
            float4 v[4];
#pragma unroll
            for (int k = 0; k < 4; k++) {
                idx[k] = tid + k * 256;
                act[k] = idx[k] < NQ;
                nib[k] = act[k]
                    ? (s_bits[idx[k] >> 3] >> ((idx[k] & 7) * 4)) & 15u
                    : 0u;
            }
#pragma unroll
            for (int k = 0; k < 4; k++)
                if (act[k])
                    v[k] = __ldcs(reinterpret_cast<const float4*>(mrow + idx[k] * 4));
#pragma unroll
            for (int k = 0; k < 4; k++) {
                if (!act[k]) continue;
                const float4 msk = s_lut[nib[k]];
                v[k].x *= msk.x;
                v[k].y *= msk.y;
                v[k].z *= msk.z;
                v[k].w *= msk.w;
                __stcs(reinterpret_cast<float4*>(orow + idx[k] * 4), v[k]);
            }
        }
    }
}

extern "C" void kernel_launch(void* const* d_in, const int* in_sizes, int n_in,
                              void* d_out, int out_size) {
    const float* mel = (const float*)d_in[0];
    const int* lengths = (const int*)d_in[1];
    float* out = (float*)d_out;

    fused_kernel<<<BATCH * CHUNKS, 256>>>(mel, lengths, out);
}